// round 5
// baseline (speedup 1.0000x reference)
#include <cuda_runtime.h>
#include <cstdint>

// T=32768, H=1024, O=1024
//   scores[t] = enc[t,:] . w_enc  (softmax-invariant decoder term dropped)
//   weights   = softmax(scores)            -> d_out[1024 .. 1024+32768)
//   output[h] = sum_t weights[t]*enc[t,h]  -> d_out[0 .. 1024)
//
// Single persistent kernel:
//   phase 1: cp.async.bulk 3-stage smem pipeline; empty-arrive right after
//            the dot consumes the stage (stage recycles at memory pace).
//   grid sync: monotonic atomic ticket (148 blocks = 1/SM, co-resident).
//   phase 2: every block computes invS, writes its own weights chunk;
//            blocks 0..127 reduce 8 output dims each.

#define T_ROWS     32768
#define HDIM       1024
#define NBLK1      148
#define NSTAGES    3
#define STG_ROWS   16
#define STG_F4     (STG_ROWS * 256)
#define STG_BYTES  (STG_ROWS * HDIM * 4)     // 65536
#define NK         14                        // ceil(222/16)

__device__ float g_escore[T_ROWS];
__device__ float g_blk_s[NBLK1];
__device__ float g_blk_acc[NBLK1 * HDIM];
__device__ unsigned int g_done;              // monotonic across graph replays

__device__ __forceinline__ uint32_t smem_u32(const void* p) {
    return (uint32_t)__cvta_generic_to_shared(p);
}
__device__ __forceinline__ void mbar_init(uint32_t a, uint32_t cnt) {
    asm volatile("mbarrier.init.shared.b64 [%0], %1;" :: "r"(a), "r"(cnt) : "memory");
}
__device__ __forceinline__ void mbar_expect_tx(uint32_t a, uint32_t bytes) {
    asm volatile("mbarrier.arrive.expect_tx.shared.b64 _, [%0], %1;" :: "r"(a), "r"(bytes) : "memory");
}
__device__ __forceinline__ void mbar_arrive(uint32_t a) {
    asm volatile("mbarrier.arrive.shared.b64 _, [%0];" :: "r"(a) : "memory");
}
__device__ __forceinline__ void mbar_wait(uint32_t a, uint32_t parity) {
    uint32_t done;
    asm volatile(
        "{ .reg .pred p;\n"
        "  mbarrier.try_wait.parity.acquire.cta.shared::cta.b64 p, [%1], %2;\n"
        "  selp.b32 %0, 1, 0, p; }"
        : "=r"(done) : "r"(a), "r"(parity) : "memory");
    if (!done) {
        asm volatile(
            "{ .reg .pred P1;\n"
            "WL_%=:\n"
            "  mbarrier.try_wait.parity.acquire.cta.shared::cta.b64 P1, [%0], %1, 0x989680;\n"
            "  @P1 bra.uni WD_%=;\n"
            "  bra.uni WL_%=;\n"
            "WD_%=: }"
            :: "r"(a), "r"(parity) : "memory");
    }
}
__device__ __forceinline__ void bulk_g2s(uint32_t dst, const void* src,
                                         uint32_t bytes, uint32_t mbar) {
    asm volatile(
        "cp.async.bulk.shared::cluster.global.mbarrier::complete_tx::bytes [%0], [%1], %2, [%3];"
        :: "r"(dst), "l"(src), "r"(bytes), "r"(mbar) : "memory");
}

__global__ __launch_bounds__(256, 1)
void fused_kernel(const float* __restrict__ enc, const float* __restrict__ attn_w,
                  float* __restrict__ out)
{
    extern __shared__ __align__(16) float4 sbuf[];   // NSTAGES * STG_F4
    __shared__ __align__(8) unsigned long long barr[2 * NSTAGES];
    __shared__ float sm_s[8];
    __shared__ float sm_red[32 * 8];
    __shared__ float sInv;

    const int tid  = threadIdx.x;
    const int lane = tid & 31;
    const int warp = tid >> 5;
    const int bid  = blockIdx.x;

    // blocks 0..59: 222 rows, 60..147: 221 rows (total 32768)
    const int row_begin = bid * 221 + min(bid, 60);
    const int cnt = 221 + (bid < 60 ? 1 : 0);

    const uint32_t bar0 = smem_u32(barr);
#define FULLB(s)  (bar0 + (uint32_t)(s) * 8u)
#define EMPTYB(s) (bar0 + (uint32_t)((s) + NSTAGES) * 8u)
    const uint32_t stage0 = smem_u32(sbuf);

    if (tid == 0) {
        for (int i = 0; i < NSTAGES; i++) mbar_init(FULLB(i), 1);
        for (int i = 0; i < NSTAGES; i++) mbar_init(EMPTYB(i), 256);
    }
    asm volatile("fence.proxy.async.shared::cta;" ::: "memory");
    __syncthreads();

    // prologue: fill all stages
    if (tid == 0) {
#pragma unroll
        for (int k = 0; k < NSTAGES; k++) {
            const int rows = min(STG_ROWS, cnt - k * STG_ROWS);
            const uint32_t bytes = (uint32_t)rows * HDIM * 4u;
            mbar_expect_tx(FULLB(k), bytes);
            bulk_g2s(stage0 + k * STG_BYTES,
                     enc + (size_t)(row_begin + k * STG_ROWS) * HDIM,
                     bytes, FULLB(k));
        }
    }

    // w_enc = attn_w[:, 1024:]
    float4 wv[8];
    {
        const float4* __restrict__ w4 = (const float4*)(attn_w + 1024);
#pragma unroll
        for (int k = 0; k < 8; k++) wv[k] = w4[k * 32 + lane];
    }

    float acc[32];
#pragma unroll
    for (int i = 0; i < 32; i++) acc[i] = 0.0f;
    float s = 0.0f;

    for (int k = 0; k < NK; k++) {
        const int st = k % NSTAGES;
        mbar_wait(FULLB(st), (uint32_t)((k / NSTAGES) & 1));

        const int rows = min(STG_ROWS, cnt - k * STG_ROWS);
        const int rr = 2 * warp;
        const float4* __restrict__ base = sbuf + st * STG_F4 + rr * 256;

        if (rr + 1 < rows) {
            float4 ev0[8], ev1[8];
#pragma unroll
            for (int j = 0; j < 8; j++) ev0[j] = base[j * 32 + lane];
#pragma unroll
            for (int j = 0; j < 8; j++) ev1[j] = base[256 + j * 32 + lane];

            float d0 = 0.0f, d1 = 0.0f;
#pragma unroll
            for (int j = 0; j < 8; j++) {
                d0 += ev0[j].x * wv[j].x; d0 += ev0[j].y * wv[j].y;
                d0 += ev0[j].z * wv[j].z; d0 += ev0[j].w * wv[j].w;
                d1 += ev1[j].x * wv[j].x; d1 += ev1[j].y * wv[j].y;
                d1 += ev1[j].z * wv[j].z; d1 += ev1[j].w * wv[j].w;
            }
            // stage data now lives in registers -> free the stage EARLY
            mbar_arrive(EMPTYB(st));

#pragma unroll
            for (int o = 16; o > 0; o >>= 1) {
                d0 += __shfl_xor_sync(0xffffffffu, d0, o);
                d1 += __shfl_xor_sync(0xffffffffu, d1, o);
            }
            const float w0 = __expf(d0);
            const float w1 = __expf(d1);
            const int grow = row_begin + k * STG_ROWS + rr;
            if (lane == 0) {
                g_escore[grow]     = w0;
                g_escore[grow + 1] = w1;
            }
            s += w0 + w1;
#pragma unroll
            for (int j = 0; j < 8; j++) {
                acc[4*j+0] += w0 * ev0[j].x; acc[4*j+0] += w1 * ev1[j].x;
                acc[4*j+1] += w0 * ev0[j].y; acc[4*j+1] += w1 * ev1[j].y;
                acc[4*j+2] += w0 * ev0[j].z; acc[4*j+2] += w1 * ev1[j].z;
                acc[4*j+3] += w0 * ev0[j].w; acc[4*j+3] += w1 * ev1[j].w;
            }
        } else if (rr < rows) {
            float4 ev0[8];
#pragma unroll
            for (int j = 0; j < 8; j++) ev0[j] = base[j * 32 + lane];
            float d0 = 0.0f;
#pragma unroll
            for (int j = 0; j < 8; j++) {
                d0 += ev0[j].x * wv[j].x; d0 += ev0[j].y * wv[j].y;
                d0 += ev0[j].z * wv[j].z; d0 += ev0[j].w * wv[j].w;
            }
            mbar_arrive(EMPTYB(st));
#pragma unroll
            for (int o = 16; o > 0; o >>= 1)
                d0 += __shfl_xor_sync(0xffffffffu, d0, o);
            const float w0 = __expf(d0);
            if (lane == 0) g_escore[row_begin + k * STG_ROWS + rr] = w0;
            s += w0;
#pragma unroll
            for (int j = 0; j < 8; j++) {
                acc[4*j+0] += w0 * ev0[j].x;
                acc[4*j+1] += w0 * ev0[j].y;
                acc[4*j+2] += w0 * ev0[j].z;
                acc[4*j+3] += w0 * ev0[j].w;
            }
        } else {
            mbar_arrive(EMPTYB(st));
        }

        // refill this stage for round k+NSTAGES
        const int kn = k + NSTAGES;
        if (tid == 0 && kn < NK) {
            mbar_wait(EMPTYB(st), (uint32_t)(((kn / NSTAGES) - 1) & 1));
            const int rows2 = min(STG_ROWS, cnt - kn * STG_ROWS);
            const uint32_t bytes = (uint32_t)rows2 * HDIM * 4u;
            mbar_expect_tx(FULLB(st), bytes);
            bulk_g2s(stage0 + st * STG_BYTES,
                     enc + (size_t)(row_begin + kn * STG_ROWS) * HDIM,
                     bytes, FULLB(st));
        }
    }

    // ---- block combine (reuse stage smem as scratch) ----
    __syncthreads();
    float4* sm_acc = sbuf;                    // 8*256 float4 = 32KB
    if (lane == 0) sm_s[warp] = s;
#pragma unroll
    for (int j = 0; j < 8; j++)
        sm_acc[warp * 256 + j * 32 + lane] =
            make_float4(acc[4*j+0], acc[4*j+1], acc[4*j+2], acc[4*j+3]);
    __syncthreads();

    float4 rsum = make_float4(0.f, 0.f, 0.f, 0.f);
#pragma unroll
    for (int w = 0; w < 8; w++) {
        const float4 a = sm_acc[w * 256 + tid];
        rsum.x += a.x; rsum.y += a.y; rsum.z += a.z; rsum.w += a.w;
    }
    ((float4*)g_blk_acc)[bid * 256 + tid] = rsum;

    if (tid == 0) {
        float S = 0.0f;
#pragma unroll
        for (int w = 0; w < 8; w++) S += sm_s[w];
        g_blk_s[bid] = S;
    }

    // ---- grid-wide sync (monotonic ticket; survives graph replays) ----
    __threadfence();
    __syncthreads();
    if (tid == 0) {
        const unsigned int ticket = atomicAdd(&g_done, 1u);
        const unsigned int target = (ticket / (unsigned)NBLK1) * (unsigned)NBLK1
                                    + (unsigned)NBLK1;
        unsigned int v;
        do {
            asm volatile("ld.global.acquire.gpu.u32 %0, [%1];"
                         : "=r"(v) : "l"(&g_done));
        } while (v < target);
    }
    __syncthreads();
    __threadfence();

    // ---- phase 2: finalize ----
    // invS: every block reduces the 148 per-block sums (L2 hits).
    {
        float v = (tid < NBLK1) ? g_blk_s[tid] : 0.0f;
#pragma unroll
        for (int o = 16; o > 0; o >>= 1)
            v += __shfl_xor_sync(0xffffffffu, v, o);
        if (lane == 0) sm_s[warp] = v;
        __syncthreads();
        if (tid == 0) {
            float S = 0.0f;
#pragma unroll
            for (int j = 0; j < 8; j++) S += sm_s[j];
            sInv = 1.0f / S;
        }
        __syncthreads();
    }
    const float invS = sInv;

    // weights: this block rewrites its own rows (escore chunk is L2-hot).
    if (tid < cnt)
        out[1024 + row_begin + tid] = g_escore[row_begin + tid] * invS;

    // output: blocks 0..127 reduce 8 dims each over 148 partials.
    if (bid < 128) {
        const int dl = tid & 7;               // dim within group
        const int ch = tid >> 3;              // 0..31
        float r = 0.0f;
#pragma unroll
        for (int j = 0; j < 5; j++) {
            const int idx = ch + 32 * j;
            if (idx < NBLK1) r += g_blk_acc[idx * HDIM + bid * 8 + dl];
        }
        sm_red[ch * 8 + dl] = r;
        __syncthreads();
        if (tid < 8) {
            float t2 = 0.0f;
#pragma unroll
            for (int j = 0; j < 32; j++) t2 += sm_red[j * 8 + tid];
            out[bid * 8 + tid] = t2 * invS;
        }
    }
}

extern "C" void kernel_launch(void* const* d_in, const int* in_sizes, int n_in,
                              void* d_out, int out_size)
{
    // inputs: [0]=dec_h (unused), [1]=enc, [2]=attn_w, [3]=attn_b (unused)
    const float* enc    = (const float*)d_in[1];
    const float* attn_w = (const float*)d_in[2];
    float* out = (float*)d_out;

    cudaFuncSetAttribute(fused_kernel,
                         cudaFuncAttributeMaxDynamicSharedMemorySize,
                         NSTAGES * STG_BYTES);
    fused_kernel<<<NBLK1, 256, NSTAGES * STG_BYTES>>>(enc, attn_w, out);
}

// round 6
// speedup vs baseline: 1.0088x; 1.0088x over previous
#include <cuda_runtime.h>
#include <cstdint>

// T=32768, H=1024, O=1024
//   scores[t] = enc[t,:] . w_enc  (softmax-invariant decoder term dropped)
//   weights   = softmax(scores)            -> d_out[1024 .. 1024+32768)
//   output[h] = sum_t weights[t]*enc[t,h]  -> d_out[0 .. 1024)
//
// Single persistent kernel, warp-specialized:
//   warp 8 (producer): wait-empty -> cp.async.bulk, nothing else. TMA issue
//     decoupled from compute -> stages recycle at memory pace.
//   warps 0..7 (consumers): LDS stage rows -> dot -> arrive-empty -> exp ->
//     accumulate.
//   grid sync: monotonic atomic ticket (148 blocks = 1/SM, co-resident).
//   phase 2: invS, weights rewrite, output reduction.

#define T_ROWS     32768
#define HDIM       1024
#define NBLK1      148
#define NTHREADS   288                       // 8 consumer warps + 1 producer
#define NSTAGES    3
#define STG_ROWS   16
#define STG_F4     (STG_ROWS * 256)
#define STG_BYTES  (STG_ROWS * HDIM * 4)     // 65536
#define NK         14                        // ceil(222/16)

__device__ float g_escore[T_ROWS];
__device__ float g_blk_s[NBLK1];
__device__ float g_blk_acc[NBLK1 * HDIM];
__device__ unsigned int g_done;              // monotonic across graph replays

__device__ __forceinline__ uint32_t smem_u32(const void* p) {
    return (uint32_t)__cvta_generic_to_shared(p);
}
__device__ __forceinline__ void mbar_init(uint32_t a, uint32_t cnt) {
    asm volatile("mbarrier.init.shared.b64 [%0], %1;" :: "r"(a), "r"(cnt) : "memory");
}
__device__ __forceinline__ void mbar_expect_tx(uint32_t a, uint32_t bytes) {
    asm volatile("mbarrier.arrive.expect_tx.shared.b64 _, [%0], %1;" :: "r"(a), "r"(bytes) : "memory");
}
__device__ __forceinline__ void mbar_arrive(uint32_t a) {
    asm volatile("mbarrier.arrive.shared.b64 _, [%0];" :: "r"(a) : "memory");
}
__device__ __forceinline__ void mbar_wait(uint32_t a, uint32_t parity) {
    uint32_t done;
    asm volatile(
        "{ .reg .pred p;\n"
        "  mbarrier.try_wait.parity.acquire.cta.shared::cta.b64 p, [%1], %2;\n"
        "  selp.b32 %0, 1, 0, p; }"
        : "=r"(done) : "r"(a), "r"(parity) : "memory");
    if (!done) {
        asm volatile(
            "{ .reg .pred P1;\n"
            "WL_%=:\n"
            "  mbarrier.try_wait.parity.acquire.cta.shared::cta.b64 P1, [%0], %1, 0x989680;\n"
            "  @P1 bra.uni WD_%=;\n"
            "  bra.uni WL_%=;\n"
            "WD_%=: }"
            :: "r"(a), "r"(parity) : "memory");
    }
}
__device__ __forceinline__ void bulk_g2s(uint32_t dst, const void* src,
                                         uint32_t bytes, uint32_t mbar) {
    asm volatile(
        "cp.async.bulk.shared::cluster.global.mbarrier::complete_tx::bytes [%0], [%1], %2, [%3];"
        :: "r"(dst), "l"(src), "r"(bytes), "r"(mbar) : "memory");
}

__global__ __launch_bounds__(NTHREADS, 1)
void fused_kernel(const float* __restrict__ enc, const float* __restrict__ attn_w,
                  float* __restrict__ out)
{
    extern __shared__ __align__(16) float4 sbuf[];   // NSTAGES * STG_F4
    __shared__ __align__(8) unsigned long long barr[2 * NSTAGES];
    __shared__ float sm_s[8];
    __shared__ float sm_red[32 * 8];
    __shared__ float sInv;

    const int tid  = threadIdx.x;
    const int lane = tid & 31;
    const int warp = tid >> 5;
    const int bid  = blockIdx.x;

    // blocks 0..59: 222 rows, 60..147: 221 rows (total 32768)
    const int row_begin = bid * 221 + min(bid, 60);
    const int cnt = 221 + (bid < 60 ? 1 : 0);

    const uint32_t bar0 = smem_u32(barr);
#define FULLB(s)  (bar0 + (uint32_t)(s) * 8u)
#define EMPTYB(s) (bar0 + (uint32_t)((s) + NSTAGES) * 8u)
    const uint32_t stage0 = smem_u32(sbuf);

    if (tid == 0) {
        for (int i = 0; i < NSTAGES; i++) mbar_init(FULLB(i), 1);
        for (int i = 0; i < NSTAGES; i++) mbar_init(EMPTYB(i), 8);
    }
    asm volatile("fence.proxy.async.shared::cta;" ::: "memory");
    __syncthreads();

    if (warp == 8) {
        // ---------------- producer warp ----------------
        if (lane == 0) {
            int st = 0, ph = 1;                      // first empty-waits pass
            for (int k = 0; k < NK; k++) {
                mbar_wait(EMPTYB(st), (uint32_t)ph);
                const int rows = min(STG_ROWS, cnt - k * STG_ROWS);
                const uint32_t bytes = (uint32_t)rows * HDIM * 4u;
                mbar_expect_tx(FULLB(st), bytes);
                bulk_g2s(stage0 + st * STG_BYTES,
                         enc + (size_t)(row_begin + k * STG_ROWS) * HDIM,
                         bytes, FULLB(st));
                if (++st == NSTAGES) { st = 0; ph ^= 1; }
            }
        }
    } else {
        // ---------------- consumer warps ----------------
        float4 wv[8];
        {
            const float4* __restrict__ w4 = (const float4*)(attn_w + 1024);
#pragma unroll
            for (int k = 0; k < 8; k++) wv[k] = w4[k * 32 + lane];
        }

        float acc[32];
#pragma unroll
        for (int i = 0; i < 32; i++) acc[i] = 0.0f;
        float s = 0.0f;

        int cst = 0, cph = 0;
        for (int k = 0; k < NK; k++) {
            mbar_wait(FULLB(cst), (uint32_t)cph);

            const int rows = min(STG_ROWS, cnt - k * STG_ROWS);
            const int rr = 2 * warp;
            const float4* __restrict__ base = sbuf + cst * STG_F4 + rr * 256;

            if (rr + 1 < rows) {
                float4 ev0[8], ev1[8];
#pragma unroll
                for (int j = 0; j < 8; j++) ev0[j] = base[j * 32 + lane];
#pragma unroll
                for (int j = 0; j < 8; j++) ev1[j] = base[256 + j * 32 + lane];

                float d0 = 0.0f, d1 = 0.0f;
#pragma unroll
                for (int j = 0; j < 8; j++) {
                    d0 += ev0[j].x * wv[j].x; d0 += ev0[j].y * wv[j].y;
                    d0 += ev0[j].z * wv[j].z; d0 += ev0[j].w * wv[j].w;
                    d1 += ev1[j].x * wv[j].x; d1 += ev1[j].y * wv[j].y;
                    d1 += ev1[j].z * wv[j].z; d1 += ev1[j].w * wv[j].w;
                }
                // stage contents now in registers -> release stage
                if (lane == 0) mbar_arrive(EMPTYB(cst));

#pragma unroll
                for (int o = 16; o > 0; o >>= 1) {
                    d0 += __shfl_xor_sync(0xffffffffu, d0, o);
                    d1 += __shfl_xor_sync(0xffffffffu, d1, o);
                }
                const float w0 = __expf(d0);
                const float w1 = __expf(d1);
                const int grow = row_begin + k * STG_ROWS + rr;
                if (lane == 0) {
                    g_escore[grow]     = w0;
                    g_escore[grow + 1] = w1;
                }
                s += w0 + w1;
#pragma unroll
                for (int j = 0; j < 8; j++) {
                    acc[4*j+0] += w0 * ev0[j].x; acc[4*j+0] += w1 * ev1[j].x;
                    acc[4*j+1] += w0 * ev0[j].y; acc[4*j+1] += w1 * ev1[j].y;
                    acc[4*j+2] += w0 * ev0[j].z; acc[4*j+2] += w1 * ev1[j].z;
                    acc[4*j+3] += w0 * ev0[j].w; acc[4*j+3] += w1 * ev1[j].w;
                }
            } else if (rr < rows) {
                float4 ev0[8];
#pragma unroll
                for (int j = 0; j < 8; j++) ev0[j] = base[j * 32 + lane];
                float d0 = 0.0f;
#pragma unroll
                for (int j = 0; j < 8; j++) {
                    d0 += ev0[j].x * wv[j].x; d0 += ev0[j].y * wv[j].y;
                    d0 += ev0[j].z * wv[j].z; d0 += ev0[j].w * wv[j].w;
                }
                if (lane == 0) mbar_arrive(EMPTYB(cst));
#pragma unroll
                for (int o = 16; o > 0; o >>= 1)
                    d0 += __shfl_xor_sync(0xffffffffu, d0, o);
                const float w0 = __expf(d0);
                if (lane == 0) g_escore[row_begin + k * STG_ROWS + rr] = w0;
                s += w0;
#pragma unroll
                for (int j = 0; j < 8; j++) {
                    acc[4*j+0] += w0 * ev0[j].x;
                    acc[4*j+1] += w0 * ev0[j].y;
                    acc[4*j+2] += w0 * ev0[j].z;
                    acc[4*j+3] += w0 * ev0[j].w;
                }
            } else {
                if (lane == 0) mbar_arrive(EMPTYB(cst));
            }

            if (++cst == NSTAGES) { cst = 0; cph ^= 1; }
        }

        if (lane == 0) sm_s[warp] = s;

        // stash accumulators for block combine (written after barrier below)
        // store into smem scratch now (stage buffers are done being reused
        // only after all consumers pass their last arrive; producer issues no
        // more TMA after k=NK-1, so after __syncthreads it's safe)
        // -> handled after the sync.
#pragma unroll
        for (int i = 0; i < 32; i++) acc[i] = acc[i];  // keep live
        // fallthrough to common code with acc live
        // ---- block combine ----
        __syncthreads();                       // consumers + producer
        float4* sm_acc = sbuf;
#pragma unroll
        for (int j = 0; j < 8; j++)
            sm_acc[warp * 256 + j * 32 + lane] =
                make_float4(acc[4*j+0], acc[4*j+1], acc[4*j+2], acc[4*j+3]);
        goto combined;
    }
    __syncthreads();                           // producer path joins here
combined:
    __syncthreads();

    if (tid < 256) {
        float4* sm_acc = sbuf;
        float4 rsum = make_float4(0.f, 0.f, 0.f, 0.f);
#pragma unroll
        for (int w = 0; w < 8; w++) {
            const float4 a = sm_acc[w * 256 + tid];
            rsum.x += a.x; rsum.y += a.y; rsum.z += a.z; rsum.w += a.w;
        }
        ((float4*)g_blk_acc)[bid * 256 + tid] = rsum;
    }
    if (tid == 0) {
        float S = 0.0f;
#pragma unroll
        for (int w = 0; w < 8; w++) S += sm_s[w];
        g_blk_s[bid] = S;
    }

    // ---- grid-wide sync (monotonic ticket; survives graph replays) ----
    __threadfence();
    __syncthreads();
    if (tid == 0) {
        const unsigned int ticket = atomicAdd(&g_done, 1u);
        const unsigned int target = (ticket / (unsigned)NBLK1) * (unsigned)NBLK1
                                    + (unsigned)NBLK1;
        unsigned int v;
        do {
            asm volatile("ld.global.acquire.gpu.u32 %0, [%1];"
                         : "=r"(v) : "l"(&g_done));
        } while (v < target);
    }
    __syncthreads();
    __threadfence();

    // ---- phase 2: finalize ----
    {
        float v = (tid < NBLK1) ? g_blk_s[tid] : 0.0f;
        if (tid < 256) {
#pragma unroll
            for (int o = 16; o > 0; o >>= 1)
                v += __shfl_xor_sync(0xffffffffu, v, o);
            if (lane == 0) sm_s[warp] = v;
        }
        __syncthreads();
        if (tid == 0) {
            float S = 0.0f;
#pragma unroll
            for (int j = 0; j < 8; j++) S += sm_s[j];
            sInv = 1.0f / S;
        }
        __syncthreads();
    }
    const float invS = sInv;

    // weights: rewrite this block's rows (escore chunk is L2-hot).
    if (tid < cnt)
        out[1024 + row_begin + tid] = g_escore[row_begin + tid] * invS;

    // output: blocks 0..127 reduce 8 dims each over 148 partials.
    if (bid < 128 && tid < 256) {
        const int dl = tid & 7;
        const int ch = tid >> 3;              // 0..31
        float r = 0.0f;
#pragma unroll
        for (int j = 0; j < 5; j++) {
            const int idx = ch + 32 * j;
            if (idx < NBLK1) r += g_blk_acc[idx * HDIM + bid * 8 + dl];
        }
        sm_red[ch * 8 + dl] = r;
        __syncthreads();
        if (tid < 8) {
            float t2 = 0.0f;
#pragma unroll
            for (int j = 0; j < 32; j++) t2 += sm_red[j * 8 + tid];
            out[bid * 8 + tid] = t2 * invS;
        }
    }
}

extern "C" void kernel_launch(void* const* d_in, const int* in_sizes, int n_in,
                              void* d_out, int out_size)
{
    // inputs: [0]=dec_h (unused), [1]=enc, [2]=attn_w, [3]=attn_b (unused)
    const float* enc    = (const float*)d_in[1];
    const float* attn_w = (const float*)d_in[2];
    float* out = (float*)d_out;

    cudaFuncSetAttribute(fused_kernel,
                         cudaFuncAttributeMaxDynamicSharedMemorySize,
                         NSTAGES * STG_BYTES);
    fused_kernel<<<NBLK1, NTHREADS, NSTAGES * STG_BYTES>>>(enc, attn_w, out);
}